// round 3
// baseline (speedup 1.0000x reference)
#include <cuda_runtime.h>
#include <cuda_fp16.h>
#include <cstdint>

// ---------------- problem constants ----------------
#define N_IMG 32
#define HW_DIM 112
#define C_IN 128
#define C_OUT 256
#define PIX_PER_IMG (HW_DIM * HW_DIM)            // 12544
#define TOT_PIX (N_IMG * PIX_PER_IMG)            // 401408
#define TILE_M 128
#define NUM_TILES (TOT_PIX / TILE_M)             // 3136
#define K_CHUNK 64                                // halves per chunk
#define NUM_CHUNKS 18                             // 9 taps * 2

// ---------------- arch-feature guard ----------------
// The harness compiles a portable compute_103 PTX pass alongside sm_103a.
// tcgen05 only exists on the arch-specific ('a') target; stub it out elsewhere.
#if defined(__CUDA_ARCH_FEAT_SM103_ALL) || defined(__CUDA_ARCH_FEAT_SM100_ALL) || \
    defined(__CUDA_ARCH_SPECIFIC__) || defined(__CUDA_ARCH_FAMILY_SPECIFIC__)
#define HAS_TCGEN05 1
#else
#define HAS_TCGEN05 0
#endif

// ---------------- smem layout ----------------
#define SM_TMEM 0
#define SM_MBAR 8
#define SM_A    1024                              // 128 rows * 128B = 16384
#define SM_B    17408                             // 256 rows * 128B = 32768
#define SM_TOTAL 50176
#define SM_EPI  1024                              // reuse A region: 128*33 floats
#define SM_BIAS 20480                             // 256 floats

// scratch (device globals: allocation-free scratch per harness rules)
__device__ __half Xh_g[(size_t)TOT_PIX * C_IN];               // ~103 MB
__device__ __half Wq_g[9 * 2 * C_OUT * K_CHUNK];              // 576 KB

// ---------------- ptx helpers (inlined, guarded) ----------------
__device__ __forceinline__ uint32_t smem_u32(const void* p) {
    uint32_t a;
    asm("{ .reg .u64 t; cvta.to.shared.u64 t, %1; cvt.u32.u64 %0, t; }"
        : "=r"(a) : "l"(p));
    return a;
}

__device__ __forceinline__ bool elect_one() {
    uint32_t pred;
    asm volatile(
        "{\n\t.reg .pred p;\n\telect.sync _|p, 0xFFFFFFFF;\n\t"
        "selp.b32 %0, 1, 0, p;\n\t}" : "=r"(pred));
    return pred != 0;
}

#define SW128(off) ((off) ^ (((off) >> 3) & 0x70))

__device__ __forceinline__ uint64_t make_desc_sw128(uint32_t addr) {
    // K-major SW128: layout=2, version=1, SBO=64 (1024B / 8-row group), LBO=1
    uint64_t d = ((uint64_t)2 << 61) | ((uint64_t)1 << 46) |
                 ((uint64_t)64 << 32) | ((uint64_t)1 << 16);
    d |= (uint64_t)((addr >> 4) & 0x3FFF);
    return d;
}

#if HAS_TCGEN05

#define TCGEN05_ALLOC(smem_addr, nCols) \
    asm volatile("tcgen05.alloc.cta_group::1.sync.aligned.shared::cta.b32 [%0], %1;" \
                 :: "r"((uint32_t)(smem_addr)), "r"((uint32_t)(nCols)) : "memory")
#define TCGEN05_DEALLOC(tmem_addr, nCols) \
    asm volatile("tcgen05.dealloc.cta_group::1.sync.aligned.b32 %0, %1;" \
                 :: "r"(tmem_addr), "r"((uint32_t)(nCols)))
#define TCGEN05_RELINQUISH() \
    asm volatile("tcgen05.relinquish_alloc_permit.cta_group::1.sync.aligned;")
#define TCGEN05_COMMIT(mbar) \
    asm volatile("tcgen05.commit.cta_group::1.mbarrier::arrive::one.shared::cluster.b64 [%0];" \
                 :: "r"((uint32_t)(mbar)) : "memory")
#define TCGEN05_FENCE_AFTER() \
    asm volatile("tcgen05.fence::after_thread_sync;" ::: "memory")
#define TCGEN05_WAIT_LD() \
    asm volatile("tcgen05.wait::ld.sync.aligned;" ::: "memory")

#define TCGEN05_LD_32X32B_X32(r, tmem_addr) \
    asm volatile( \
        "tcgen05.ld.sync.aligned.32x32b.x32.b32 " \
        "{%0, %1, %2, %3, %4, %5, %6, %7, " \
        " %8, %9, %10, %11, %12, %13, %14, %15, " \
        " %16, %17, %18, %19, %20, %21, %22, %23, " \
        " %24, %25, %26, %27, %28, %29, %30, %31}, [%32];" \
        : "=r"((r)[0]),  "=r"((r)[1]),  "=r"((r)[2]),  "=r"((r)[3]), \
          "=r"((r)[4]),  "=r"((r)[5]),  "=r"((r)[6]),  "=r"((r)[7]), \
          "=r"((r)[8]),  "=r"((r)[9]),  "=r"((r)[10]), "=r"((r)[11]), \
          "=r"((r)[12]), "=r"((r)[13]), "=r"((r)[14]), "=r"((r)[15]), \
          "=r"((r)[16]), "=r"((r)[17]), "=r"((r)[18]), "=r"((r)[19]), \
          "=r"((r)[20]), "=r"((r)[21]), "=r"((r)[22]), "=r"((r)[23]), \
          "=r"((r)[24]), "=r"((r)[25]), "=r"((r)[26]), "=r"((r)[27]), \
          "=r"((r)[28]), "=r"((r)[29]), "=r"((r)[30]), "=r"((r)[31]) \
        : "r"(tmem_addr))

// SS-mode f16 MMA, cta_group::1 (A desc + B desc in SMEM, D in TMEM)
__device__ __forceinline__ void mma_f16_ss(uint32_t d_tmem, uint64_t a_desc,
                                           uint64_t b_desc, uint32_t idesc,
                                           uint32_t enable_d) {
    asm volatile(
        "{\n\t.reg .pred p;\n\t"
        "setp.ne.u32 p, %4, 0;\n\t"
        "tcgen05.mma.cta_group::1.kind::f16 [%0], %1, %2, %3, p;\n\t}"
        :: "r"(d_tmem), "l"(a_desc), "l"(b_desc), "r"(idesc), "r"(enable_d)
        : "memory");
}

#else  // portable pass stubs (never executed on GB300: exact-match cubin wins)

#define TCGEN05_ALLOC(smem_addr, nCols)      do {} while (0)
#define TCGEN05_DEALLOC(tmem_addr, nCols)    do {} while (0)
#define TCGEN05_RELINQUISH()                 do {} while (0)
#define TCGEN05_COMMIT(mbar)                 do {} while (0)
#define TCGEN05_FENCE_AFTER()                do {} while (0)
#define TCGEN05_WAIT_LD()                    do {} while (0)
#define TCGEN05_LD_32X32B_X32(r, tmem_addr) \
    do { _Pragma("unroll") for (int _i = 0; _i < 32; _i++) (r)[_i] = 0u; } while (0)

__device__ __forceinline__ void mma_f16_ss(uint32_t, uint64_t, uint64_t,
                                           uint32_t, uint32_t) {}

#endif  // HAS_TCGEN05

#define FENCE_PROXY_ASYNC_SHARED() \
    asm volatile("fence.proxy.async.shared::cta;" ::: "memory")

#define MBARRIER_INIT(mbar, count) \
    asm volatile("mbarrier.init.shared.b64 [%0], %1;" \
                 :: "r"((uint32_t)(mbar)), "r"((uint32_t)(count)) : "memory")

#define MBARRIER_WAIT_PARITY(mbar_addr, phase_parity) do { \
    uint32_t _mbar = (uint32_t)(mbar_addr); \
    uint32_t _parity = (uint32_t)(phase_parity); \
    uint32_t _done; \
    asm volatile( \
        "{\n\t.reg .pred p;\n\t" \
        "mbarrier.try_wait.parity.acquire.cta.shared::cta.b64 p, [%1], %2;\n\t" \
        "selp.b32 %0, 1, 0, p;\n\t}" \
        : "=r"(_done) : "r"(_mbar), "r"(_parity) : "memory"); \
    if (!_done) { \
        asm volatile( \
            "{\n\t.reg .pred P1;\n\t" \
            "WAIT_LOOP_%=:\n\t" \
            "mbarrier.try_wait.parity.acquire.cta.shared::cta.b64 P1, [%0], %1, 0x989680;\n\t" \
            "@P1 bra.uni WAIT_DONE_%=;\n\t" \
            "bra.uni WAIT_LOOP_%=;\n\t" \
            "WAIT_DONE_%=:\n\t}" \
            :: "r"(_mbar), "r"(_parity) : "memory"); \
    } \
} while (0)

// idesc: F32 accum (1<<4), FP16 a/b (0), N=256 -> (32<<17), M=128 -> (8<<24)
#define MMA_IDESC 0x8400010u

// ---------------- prep kernels ----------------
__global__ void convert_x_kernel(const float4* __restrict__ x, int n4) {
    int i = blockIdx.x * 256 + threadIdx.x;
    if (i < n4) {
        float4 v = x[i];
        __half2 h0 = __floats2half2_rn(v.x, v.y);
        __half2 h1 = __floats2half2_rn(v.z, v.w);
        uint2 u;
        u.x = *reinterpret_cast<uint32_t*>(&h0);
        u.y = *reinterpret_cast<uint32_t*>(&h1);
        reinterpret_cast<uint2*>(Xh_g)[i] = u;
    }
}

// pack sign(W) as half into [tap][chunk][co][64] (fully contiguous B tiles)
__global__ void quant_w_kernel(const float* __restrict__ W) {
    int o = blockIdx.x * 256 + threadIdx.x;     // 0 .. 294911
    if (o < 9 * 2 * C_OUT * K_CHUNK) {
        int col = o & 63;
        int co = (o >> 6) & 255;
        int tc = o >> 14;                       // tap*2 + chunk
        int tap = tc >> 1, ch = tc & 1;
        int ci = ch * 64 + col;
        float w = W[(tap * C_IN + ci) * C_OUT + co];
        Wq_g[o] = __float2half(w > 0.f ? 1.f : (w < 0.f ? -1.f : 0.f));
    }
}

// ---------------- main implicit-GEMM conv kernel ----------------
__global__ void __launch_bounds__(256, 2)
bconv_main_kernel(const float* __restrict__ bias, float* __restrict__ out) {
    extern __shared__ char smem[];
    uint32_t smem_base = smem_u32(smem);
    int tid = threadIdx.x;
    int wid = tid >> 5, lid = tid & 31;

    if (wid == 0) {
        TCGEN05_ALLOC(smem_base + SM_TMEM, 256);
        TCGEN05_RELINQUISH();
    }
    if (tid == 0) MBARRIER_INIT(smem_base + SM_MBAR, 1);
    __syncthreads();
    uint32_t tmem_base;
    asm volatile("ld.shared.b32 %0, [%1];" : "=r"(tmem_base)
                 : "r"(smem_base + SM_TMEM));

    int pix_base = blockIdx.x * TILE_M;

    // per-thread A-fill coordinates: 4 items, each (row p, 16B segment)
    int hA[4], wA[4], segA[4], pA[4];
    size_t baseA[4];
    #pragma unroll
    for (int i = 0; i < 4; i++) {
        int item = tid + i * 256;
        int p = item >> 3;
        segA[i] = item & 7;
        pA[i] = p;
        int gp = pix_base + p;
        int n = gp / PIX_PER_IMG;
        int r = gp % PIX_PER_IMG;
        hA[i] = r / HW_DIM;
        wA[i] = r % HW_DIM;
        baseA[i] = (size_t)n * PIX_PER_IMG * C_IN;
    }

    uint64_t a_desc_base = make_desc_sw128(smem_base + SM_A);
    uint64_t b_desc_base = make_desc_sw128(smem_base + SM_B);

    for (int c = 0; c < NUM_CHUNKS; c++) {
        int tap = c >> 1, half_k = c & 1;
        int kh = tap / 3 - 1, kw = tap % 3 - 1;

        // ---- fill A tile: 128 rows x 64 halves (SW128) ----
        #pragma unroll
        for (int i = 0; i < 4; i++) {
            int hh = hA[i] + kh, ww = wA[i] + kw;
            float4 v = make_float4(0.f, 0.f, 0.f, 0.f);
            if ((unsigned)hh < (unsigned)HW_DIM && (unsigned)ww < (unsigned)HW_DIM) {
                const float4* src = reinterpret_cast<const float4*>(
                    Xh_g + baseA[i] + ((size_t)hh * HW_DIM + ww) * C_IN +
                    half_k * 64 + segA[i] * 8);
                v = *src;
            }
            uint32_t off = (uint32_t)pA[i] * 128 + segA[i] * 16;
            *reinterpret_cast<float4*>(smem + SM_A + SW128(off)) = v;
        }

        // ---- fill B tile: 256 rows x 64 halves (SW128), contiguous source ----
        const float4* wsrc = reinterpret_cast<const float4*>(
            Wq_g + (size_t)(tap * 2 + half_k) * C_OUT * K_CHUNK);
        #pragma unroll
        for (int i = 0; i < 8; i++) {
            int item = tid + i * 256;                 // 0..2047
            uint32_t off = (uint32_t)(item >> 3) * 128 + (item & 7) * 16;
            *reinterpret_cast<float4*>(smem + SM_B + SW128(off)) = wsrc[item];
        }

        FENCE_PROXY_ASYNC_SHARED();
        __syncthreads();

        if (wid == 0 && elect_one()) {
            #pragma unroll
            for (int s = 0; s < 4; s++) {            // K=64 -> 4x K=16 MMAs
                mma_f16_ss(tmem_base, a_desc_base + s * 2, b_desc_base + s * 2,
                           MMA_IDESC, (uint32_t)((c > 0) || (s > 0)));
            }
            TCGEN05_COMMIT(smem_base + SM_MBAR);
        }
        // wait for MMA completion (also makes SMEM safe to overwrite)
        MBARRIER_WAIT_PARITY(smem_base + SM_MBAR, c & 1);
    }

    TCGEN05_FENCE_AFTER();

    // ---- epilogue: TMEM -> SMEM transpose -> coalesced STG ----
    float* bsm = reinterpret_cast<float*>(smem + SM_BIAS);
    bsm[tid] = bias[tid];                            // 256 threads, 256 channels
    __syncthreads();
    float* tbuf = reinterpret_cast<float*>(smem + SM_EPI);

    for (int cb = 0; cb < 8; cb++) {                 // 8 blocks of 32 columns
        if (wid < 4) {
            uint32_t regs[32];
            TCGEN05_LD_32X32B_X32(regs, tmem_base + cb * 32);
            TCGEN05_WAIT_LD();
            int row = wid * 32 + lid;
            #pragma unroll
            for (int j = 0; j < 32; j++)
                tbuf[row * 33 + j] = __uint_as_float(regs[j]) + bsm[cb * 32 + j];
        }
        __syncthreads();
        #pragma unroll
        for (int i = 0; i < 16; i++) {
            int item = tid + i * 256;                // 128 pix x 32 cols
            int p = item >> 5, cc = item & 31;
            out[(size_t)(pix_base + p) * C_OUT + cb * 32 + cc] = tbuf[p * 33 + cc];
        }
        __syncthreads();
    }

    if (wid == 0) {
        TCGEN05_DEALLOC(tmem_base, 256);
    }
}

// ---------------- launch ----------------
extern "C" void kernel_launch(void* const* d_in, const int* in_sizes, int n_in,
                              void* d_out, int out_size) {
    const float* x = (const float*)d_in[0];
    const float* W = (const float*)d_in[1];
    const float* b = (const float*)d_in[2];
    float* out = (float*)d_out;

    cudaFuncSetAttribute(bconv_main_kernel,
                         cudaFuncAttributeMaxDynamicSharedMemorySize, SM_TOTAL);

    int n4 = (TOT_PIX * C_IN) / 4;                   // 12845056
    convert_x_kernel<<<n4 / 256, 256>>>(reinterpret_cast<const float4*>(x), n4);
    quant_w_kernel<<<(9 * 2 * C_OUT * K_CHUNK) / 256, 256>>>(W);
    bconv_main_kernel<<<NUM_TILES, 256, SM_TOTAL>>>(b, out);
}

// round 5
// speedup vs baseline: 1.0292x; 1.0292x over previous
#include <cuda_runtime.h>
#include <cuda_fp16.h>
#include <cstdint>

// ---------------- problem constants ----------------
#define N_IMG 32
#define HW_DIM 112
#define C_IN 128
#define C_OUT 256
#define PIX_PER_IMG (HW_DIM * HW_DIM)            // 12544
#define TOT_PIX (N_IMG * PIX_PER_IMG)            // 401408
#define TILE_M 128
#define NUM_TILES (TOT_PIX / TILE_M)             // 3136
#define NUM_PAIRS (NUM_TILES / 2)                // 1568 CTAs, 2 M-tiles each
#define K_CHUNK 64                                // halves per chunk
#define NUM_CHUNKS 18                             // 9 taps * 2

// ---------------- arch-feature guard ----------------
#if defined(__CUDA_ARCH_FEAT_SM103_ALL) || defined(__CUDA_ARCH_FEAT_SM100_ALL) || \
    defined(__CUDA_ARCH_SPECIFIC__) || defined(__CUDA_ARCH_FAMILY_SPECIFIC__)
#define HAS_TCGEN05 1
#else
#define HAS_TCGEN05 0
#endif

// ---------------- smem layout (bytes) ----------------
#define SM_TMEM  0
#define SM_MBAR0 8
#define SM_MBAR1 16
#define SM_A     1024                 // A[buf][tile]: 4 x 16384 -> ends 66560
#define A_TILE_B 16384
#define SM_B     66560                // B[buf]: 2 x 32768 -> ends 132096
#define B_TILE_B 32768
#define SM_BIAS  132096               // 256 floats -> 133120
#define SM_EPI   1024                 // epilogue reuses A region (128*33*4 = 16896)
#define SM_TOTAL 133632

// scratch (device globals: allocation-free scratch per harness rules)
__device__ __half Xh_g[(size_t)TOT_PIX * C_IN];               // ~103 MB (L2-resident)
__device__ __half Wq_g[9 * 2 * C_OUT * K_CHUNK];              // 576 KB

// ---------------- ptx helpers ----------------
__device__ __forceinline__ uint32_t smem_u32(const void* p) {
    uint32_t a;
    asm("{ .reg .u64 t; cvta.to.shared.u64 t, %1; cvt.u32.u64 %0, t; }"
        : "=r"(a) : "l"(p));
    return a;
}

__device__ __forceinline__ bool elect_one() {
    uint32_t pred;
    asm volatile(
        "{\n\t.reg .pred p;\n\telect.sync _|p, 0xFFFFFFFF;\n\t"
        "selp.b32 %0, 1, 0, p;\n\t}" : "=r"(pred));
    return pred != 0;
}

#define SW128(off) ((off) ^ (((off) >> 3) & 0x70))

__device__ __forceinline__ uint64_t make_desc_sw128(uint32_t addr) {
    uint64_t d = ((uint64_t)2 << 61) | ((uint64_t)1 << 46) |
                 ((uint64_t)64 << 32) | ((uint64_t)1 << 16);
    d |= (uint64_t)((addr >> 4) & 0x3FFF);
    return d;
}

#if HAS_TCGEN05

#define TCGEN05_ALLOC(smem_addr, nCols) \
    asm volatile("tcgen05.alloc.cta_group::1.sync.aligned.shared::cta.b32 [%0], %1;" \
                 :: "r"((uint32_t)(smem_addr)), "r"((uint32_t)(nCols)) : "memory")
#define TCGEN05_DEALLOC(tmem_addr, nCols) \
    asm volatile("tcgen05.dealloc.cta_group::1.sync.aligned.b32 %0, %1;" \
                 :: "r"(tmem_addr), "r"((uint32_t)(nCols)))
#define TCGEN05_RELINQUISH() \
    asm volatile("tcgen05.relinquish_alloc_permit.cta_group::1.sync.aligned;")
#define TCGEN05_COMMIT(mbar) \
    asm volatile("tcgen05.commit.cta_group::1.mbarrier::arrive::one.shared::cluster.b64 [%0];" \
                 :: "r"((uint32_t)(mbar)) : "memory")
#define TCGEN05_FENCE_AFTER() \
    asm volatile("tcgen05.fence::after_thread_sync;" ::: "memory")
#define TCGEN05_WAIT_LD() \
    asm volatile("tcgen05.wait::ld.sync.aligned;" ::: "memory")

#define TCGEN05_LD_32X32B_X32(r, tmem_addr) \
    asm volatile( \
        "tcgen05.ld.sync.aligned.32x32b.x32.b32 " \
        "{%0, %1, %2, %3, %4, %5, %6, %7, " \
        " %8, %9, %10, %11, %12, %13, %14, %15, " \
        " %16, %17, %18, %19, %20, %21, %22, %23, " \
        " %24, %25, %26, %27, %28, %29, %30, %31}, [%32];" \
        : "=r"((r)[0]),  "=r"((r)[1]),  "=r"((r)[2]),  "=r"((r)[3]), \
          "=r"((r)[4]),  "=r"((r)[5]),  "=r"((r)[6]),  "=r"((r)[7]), \
          "=r"((r)[8]),  "=r"((r)[9]),  "=r"((r)[10]), "=r"((r)[11]), \
          "=r"((r)[12]), "=r"((r)[13]), "=r"((r)[14]), "=r"((r)[15]), \
          "=r"((r)[16]), "=r"((r)[17]), "=r"((r)[18]), "=r"((r)[19]), \
          "=r"((r)[20]), "=r"((r)[21]), "=r"((r)[22]), "=r"((r)[23]), \
          "=r"((r)[24]), "=r"((r)[25]), "=r"((r)[26]), "=r"((r)[27]), \
          "=r"((r)[28]), "=r"((r)[29]), "=r"((r)[30]), "=r"((r)[31]) \
        : "r"(tmem_addr))

__device__ __forceinline__ void mma_f16_ss(uint32_t d_tmem, uint64_t a_desc,
                                           uint64_t b_desc, uint32_t idesc,
                                           uint32_t enable_d) {
    asm volatile(
        "{\n\t.reg .pred p;\n\t"
        "setp.ne.u32 p, %4, 0;\n\t"
        "tcgen05.mma.cta_group::1.kind::f16 [%0], %1, %2, %3, p;\n\t}"
        :: "r"(d_tmem), "l"(a_desc), "l"(b_desc), "r"(idesc), "r"(enable_d)
        : "memory");
}

#else  // portable-pass stubs (never executed on GB300)

#define TCGEN05_ALLOC(smem_addr, nCols)      do {} while (0)
#define TCGEN05_DEALLOC(tmem_addr, nCols)    do {} while (0)
#define TCGEN05_RELINQUISH()                 do {} while (0)
#define TCGEN05_COMMIT(mbar)                 do {} while (0)
#define TCGEN05_FENCE_AFTER()                do {} while (0)
#define TCGEN05_WAIT_LD()                    do {} while (0)
#define TCGEN05_LD_32X32B_X32(r, tmem_addr) \
    do { _Pragma("unroll") for (int _i = 0; _i < 32; _i++) (r)[_i] = 0u; } while (0)

__device__ __forceinline__ void mma_f16_ss(uint32_t, uint64_t, uint64_t,
                                           uint32_t, uint32_t) {}

#endif  // HAS_TCGEN05

#define FENCE_PROXY_ASYNC_SHARED() \
    asm volatile("fence.proxy.async.shared::cta;" ::: "memory")

#define MBARRIER_INIT(mbar, count) \
    asm volatile("mbarrier.init.shared.b64 [%0], %1;" \
                 :: "r"((uint32_t)(mbar)), "r"((uint32_t)(count)) : "memory")

#define MBARRIER_WAIT_PARITY(mbar_addr, phase_parity) do { \
    uint32_t _mbar = (uint32_t)(mbar_addr); \
    uint32_t _parity = (uint32_t)(phase_parity); \
    uint32_t _done; \
    asm volatile( \
        "{\n\t.reg .pred p;\n\t" \
        "mbarrier.try_wait.parity.acquire.cta.shared::cta.b64 p, [%1], %2;\n\t" \
        "selp.b32 %0, 1, 0, p;\n\t}" \
        : "=r"(_done) : "r"(_mbar), "r"(_parity) : "memory"); \
    if (!_done) { \
        asm volatile( \
            "{\n\t.reg .pred P1;\n\t" \
            "WAIT_LOOP_%=:\n\t" \
            "mbarrier.try_wait.parity.acquire.cta.shared::cta.b64 P1, [%0], %1, 0x989680;\n\t" \
            "@P1 bra.uni WAIT_DONE_%=;\n\t" \
            "bra.uni WAIT_LOOP_%=;\n\t" \
            "WAIT_DONE_%=:\n\t}" \
            :: "r"(_mbar), "r"(_parity) : "memory"); \
    } \
} while (0)

// idesc: F32 accum (1<<4), FP16 a/b, N=256 -> (32<<17), M=128 -> (8<<24)
#define MMA_IDESC 0x8400010u

// ---------------- prep kernels ----------------
__global__ void convert_x_kernel(const float4* __restrict__ x, int n4) {
    int i = blockIdx.x * 256 + threadIdx.x;
    if (i < n4) {
        float4 v = x[i];
        __half2 h0 = __floats2half2_rn(v.x, v.y);
        __half2 h1 = __floats2half2_rn(v.z, v.w);
        uint2 u;
        u.x = *reinterpret_cast<uint32_t*>(&h0);
        u.y = *reinterpret_cast<uint32_t*>(&h1);
        reinterpret_cast<uint2*>(Xh_g)[i] = u;
    }
}

__global__ void quant_w_kernel(const float* __restrict__ W) {
    int o = blockIdx.x * 256 + threadIdx.x;     // 0 .. 294911
    if (o < 9 * 2 * C_OUT * K_CHUNK) {
        int col = o & 63;
        int co = (o >> 6) & 255;
        int tc = o >> 14;                       // tap*2 + chunk
        int tap = tc >> 1, ch = tc & 1;
        int ci = ch * 64 + col;
        float w = W[(tap * C_IN + ci) * C_OUT + co];
        Wq_g[o] = __float2half(w > 0.f ? 1.f : (w < 0.f ? -1.f : 0.f));
    }
}

// ---------------- main implicit-GEMM conv kernel ----------------
// 2 M-tiles per CTA (share B reads), double-buffered fill/MMA pipeline.
__global__ void __launch_bounds__(256, 1)
bconv_main_kernel(const float* __restrict__ bias, float* __restrict__ out) {
    extern __shared__ char smem[];
    uint32_t smem_base = smem_u32(smem);
    int tid = threadIdx.x;
    int wid = tid >> 5, lid = tid & 31;

    if (wid == 0) {
        TCGEN05_ALLOC(smem_base + SM_TMEM, 512);
        TCGEN05_RELINQUISH();
    }
    if (tid == 0) {
        MBARRIER_INIT(smem_base + SM_MBAR0, 1);
        MBARRIER_INIT(smem_base + SM_MBAR1, 1);
    }
    __syncthreads();
    uint32_t tmem_base;
    asm volatile("ld.shared.b32 %0, [%1];" : "=r"(tmem_base)
                 : "r"(smem_base + SM_TMEM));

    // per-thread A-fill coordinates for 2 tiles x 4 items
    int hA[8], wA[8];
    size_t rowA[8];                               // Xh_g pixel-row base (elements)
    int seg = tid & 7;                            // 16B segment within 128B row
    int prow = tid >> 3;                          // A-tile row (0..31 per i-step of 32)
    #pragma unroll
    for (int t = 0; t < 2; t++) {
        int pix_base = blockIdx.x * 256 + t * 128;
        #pragma unroll
        for (int i = 0; i < 4; i++) {
            int p = prow + i * 32;
            int gp = pix_base + p;
            int n = gp / PIX_PER_IMG;
            int r = gp % PIX_PER_IMG;
            hA[t * 4 + i] = r / HW_DIM;
            wA[t * 4 + i] = r % HW_DIM;
            rowA[t * 4 + i] = (size_t)n * PIX_PER_IMG * C_IN;
        }
    }

    int ph[2] = {0, 0};
    for (int c = 0; c < NUM_CHUNKS; c++) {
        int buf = c & 1;
        int tap = c >> 1, half_k = c & 1 ? 1 : 0;
        // NOTE: chunk order = tap-major: c = tap*2 + half
        tap = c >> 1; half_k = c & 1;
        int kh = tap / 3 - 1, kw = tap % 3 - 1;
        uint32_t mbar = smem_base + (buf ? SM_MBAR1 : SM_MBAR0);

        if (c >= 2) {                             // buffer free?
            MBARRIER_WAIT_PARITY(mbar, ph[buf] & 1);
            ph[buf]++;
        }

        // ---- fill A tiles (2 x 128 rows x 64 halves, SW128) ----
        #pragma unroll
        for (int t = 0; t < 2; t++) {
            char* abuf = smem + SM_A + (buf * 2 + t) * A_TILE_B;
            #pragma unroll
            for (int i = 0; i < 4; i++) {
                int idx = t * 4 + i;
                int hh = hA[idx] + kh, ww = wA[idx] + kw;
                float4 v = make_float4(0.f, 0.f, 0.f, 0.f);
                if ((unsigned)hh < (unsigned)HW_DIM && (unsigned)ww < (unsigned)HW_DIM) {
                    v = *reinterpret_cast<const float4*>(
                        Xh_g + rowA[idx] + ((size_t)hh * HW_DIM + ww) * C_IN +
                        half_k * 64 + seg * 8);
                }
                uint32_t off = (uint32_t)(prow + i * 32) * 128 + seg * 16;
                *reinterpret_cast<float4*>(abuf + SW128(off)) = v;
            }
        }

        // ---- fill B tile (256 rows x 64 halves, SW128, contiguous src) ----
        {
            char* bbuf = smem + SM_B + buf * B_TILE_B;
            const float4* wsrc = reinterpret_cast<const float4*>(
                Wq_g + (size_t)(tap * 2 + half_k) * C_OUT * K_CHUNK);
            #pragma unroll
            for (int i = 0; i < 8; i++) {
                int item = tid + i * 256;             // 0..2047
                uint32_t off = (uint32_t)(item >> 3) * 128 + (item & 7) * 16;
                *reinterpret_cast<float4*>(bbuf + SW128(off)) = wsrc[item];
            }
        }

        FENCE_PROXY_ASYNC_SHARED();
        __syncthreads();

        if (wid == 0 && elect_one()) {
            uint64_t b_desc = make_desc_sw128(smem_base + SM_B + buf * B_TILE_B);
            uint64_t a0_desc = make_desc_sw128(smem_base + SM_A + (buf * 2 + 0) * A_TILE_B);
            uint64_t a1_desc = make_desc_sw128(smem_base + SM_A + (buf * 2 + 1) * A_TILE_B);
            uint32_t en = (c > 0);
            #pragma unroll
            for (int s = 0; s < 4; s++)
                mma_f16_ss(tmem_base, a0_desc + s * 2, b_desc + s * 2,
                           MMA_IDESC, en | (s > 0));
            #pragma unroll
            for (int s = 0; s < 4; s++)
                mma_f16_ss(tmem_base + 256, a1_desc + s * 2, b_desc + s * 2,
                           MMA_IDESC, en | (s > 0));
            TCGEN05_COMMIT(mbar);
        }
        // no wait here: next iteration fills the other buffer
    }

    // drain
    MBARRIER_WAIT_PARITY(smem_base + SM_MBAR0, ph[0] & 1);
    MBARRIER_WAIT_PARITY(smem_base + SM_MBAR1, ph[1] & 1);
    TCGEN05_FENCE_AFTER();

    // ---- epilogue: TMEM -> SMEM transpose -> coalesced STG, per tile ----
    float* bsm = reinterpret_cast<float*>(smem + SM_BIAS);
    bsm[tid] = bias[tid];
    __syncthreads();
    float* tbuf = reinterpret_cast<float*>(smem + SM_EPI);

    #pragma unroll 1
    for (int t = 0; t < 2; t++) {
        int pix_base = blockIdx.x * 256 + t * 128;
        #pragma unroll 1
        for (int cb = 0; cb < 8; cb++) {
            if (wid < 4) {
                uint32_t regs[32];
                TCGEN05_LD_32X32B_X32(regs, tmem_base + t * 256 + cb * 32);
                TCGEN05_WAIT_LD();
                int row = wid * 32 + lid;
                #pragma unroll
                for (int j = 0; j < 32; j++)
                    tbuf[row * 33 + j] = __uint_as_float(regs[j]) + bsm[cb * 32 + j];
            }
            __syncthreads();
            #pragma unroll
            for (int i = 0; i < 16; i++) {
                int item = tid + i * 256;             // 128 pix x 32 cols
                int p = item >> 5, cc = item & 31;
                out[(size_t)(pix_base + p) * C_OUT + cb * 32 + cc] = tbuf[p * 33 + cc];
            }
            __syncthreads();
        }
    }

    if (wid == 0) {
        TCGEN05_DEALLOC(tmem_base, 512);
    }
}

// ---------------- launch ----------------
extern "C" void kernel_launch(void* const* d_in, const int* in_sizes, int n_in,
                              void* d_out, int out_size) {
    const float* x = (const float*)d_in[0];
    const float* W = (const float*)d_in[1];
    const float* b = (const float*)d_in[2];
    float* out = (float*)d_out;

    cudaFuncSetAttribute(bconv_main_kernel,
                         cudaFuncAttributeMaxDynamicSharedMemorySize, SM_TOTAL);

    int n4 = (TOT_PIX * C_IN) / 4;                   // 12845056
    convert_x_kernel<<<n4 / 256, 256>>>(reinterpret_cast<const float4*>(x), n4);
    quant_w_kernel<<<(9 * 2 * C_OUT * K_CHUNK) / 256, 256>>>(W);
    bconv_main_kernel<<<NUM_PAIRS, 256, SM_TOTAL>>>(b, out);
}

// round 9
// speedup vs baseline: 1.3000x; 1.2632x over previous
#include <cuda_runtime.h>
#include <cuda_fp16.h>
#include <cstdint>

// ---------------- problem constants ----------------
#define N_IMG 32
#define HW_DIM 112
#define C_IN 128
#define C_OUT 256
#define PIX_PER_IMG (HW_DIM * HW_DIM)            // 12544
#define TOT_PIX (N_IMG * PIX_PER_IMG)            // 401408
#define NUM_PAIRS (TOT_PIX / 256)                // 1568 CTAs, 2 M-tiles each
#define K_CHUNK 64
#define NUM_CHUNKS 18                             // 9 taps * 2 halves

// ---------------- arch-feature guard ----------------
#if defined(__CUDA_ARCH_FEAT_SM103_ALL) || defined(__CUDA_ARCH_FEAT_SM100_ALL) || \
    defined(__CUDA_ARCH_SPECIFIC__) || defined(__CUDA_ARCH_FAMILY_SPECIFIC__)
#define HAS_TCGEN05 1
#else
#define HAS_TCGEN05 0
#endif

// ---------------- smem layout (bytes) ----------------
#define SM_TMEM   0
#define SM_MBAR   8                   // 3 mbarriers: 8, 16, 24
#define SM_STAGE  1024                // 3 stages x 65536
#define STAGE_BYTES 65536             // A0 16K | A1 16K | B 32K
#define A_TILE_B  16384
#define B_OFF     32768
#define SM_BIAS   (SM_STAGE + 3 * STAGE_BYTES)          // 197632
#define SM_TOTAL  (SM_BIAS + 1024)                      // 198656
#define SM_TBUF   SM_STAGE            // epilogue reuses stage0 (2 x 16896B)
#define TBUF_FLT  4224                // 128*33 floats per tile buffer

// scratch (device globals: allocation-free scratch per harness rules)
__device__ __half Xh_g[(size_t)TOT_PIX * C_IN];               // ~103 MB
__device__ __half Wq_g[NUM_CHUNKS * C_OUT * K_CHUNK];         // 576 KB

// ---------------- ptx helpers ----------------
__device__ __forceinline__ uint32_t smem_u32(const void* p) {
    uint32_t a;
    asm("{ .reg .u64 t; cvta.to.shared.u64 t, %1; cvt.u32.u64 %0, t; }"
        : "=r"(a) : "l"(p));
    return a;
}

__device__ __forceinline__ bool elect_one() {
    uint32_t pred;
    asm volatile(
        "{\n\t.reg .pred p;\n\telect.sync _|p, 0xFFFFFFFF;\n\t"
        "selp.b32 %0, 1, 0, p;\n\t}" : "=r"(pred));
    return pred != 0;
}

#define SW128(off) ((off) ^ (((off) >> 3) & 0x70))

__device__ __forceinline__ uint64_t make_desc_sw128(uint32_t addr) {
    uint64_t d = ((uint64_t)2 << 61) | ((uint64_t)1 << 46) |
                 ((uint64_t)64 << 32) | ((uint64_t)1 << 16);
    d |= (uint64_t)((addr >> 4) & 0x3FFF);
    return d;
}

// cp.async 16B with zero-fill when !ok (src_size = 0 reads nothing)
__device__ __forceinline__ void cp_async16(uint32_t smem_addr, const void* gptr,
                                           bool ok) {
    int sz = ok ? 16 : 0;
    asm volatile("cp.async.cg.shared.global [%0], [%1], 16, %2;"
                 :: "r"(smem_addr), "l"(gptr), "r"(sz) : "memory");
}
#define CP_ASYNC_COMMIT() asm volatile("cp.async.commit_group;" ::: "memory")
#define CP_ASYNC_WAIT_1() asm volatile("cp.async.wait_group 1;" ::: "memory")
#define CP_ASYNC_WAIT_0() asm volatile("cp.async.wait_group 0;" ::: "memory")

#if HAS_TCGEN05

#define TCGEN05_ALLOC(smem_addr, nCols) \
    asm volatile("tcgen05.alloc.cta_group::1.sync.aligned.shared::cta.b32 [%0], %1;" \
                 :: "r"((uint32_t)(smem_addr)), "r"((uint32_t)(nCols)) : "memory")
#define TCGEN05_DEALLOC(tmem_addr, nCols) \
    asm volatile("tcgen05.dealloc.cta_group::1.sync.aligned.b32 %0, %1;" \
                 :: "r"(tmem_addr), "r"((uint32_t)(nCols)))
#define TCGEN05_RELINQUISH() \
    asm volatile("tcgen05.relinquish_alloc_permit.cta_group::1.sync.aligned;")
#define TCGEN05_COMMIT(mbar) \
    asm volatile("tcgen05.commit.cta_group::1.mbarrier::arrive::one.shared::cluster.b64 [%0];" \
                 :: "r"((uint32_t)(mbar)) : "memory")
#define TCGEN05_FENCE_AFTER() \
    asm volatile("tcgen05.fence::after_thread_sync;" ::: "memory")
#define TCGEN05_WAIT_LD() \
    asm volatile("tcgen05.wait::ld.sync.aligned;" ::: "memory")

#define TCGEN05_LD_32X32B_X32(r, tmem_addr) \
    asm volatile( \
        "tcgen05.ld.sync.aligned.32x32b.x32.b32 " \
        "{%0, %1, %2, %3, %4, %5, %6, %7, " \
        " %8, %9, %10, %11, %12, %13, %14, %15, " \
        " %16, %17, %18, %19, %20, %21, %22, %23, " \
        " %24, %25, %26, %27, %28, %29, %30, %31}, [%32];" \
        : "=r"((r)[0]),  "=r"((r)[1]),  "=r"((r)[2]),  "=r"((r)[3]), \
          "=r"((r)[4]),  "=r"((r)[5]),  "=r"((r)[6]),  "=r"((r)[7]), \
          "=r"((r)[8]),  "=r"((r)[9]),  "=r"((r)[10]), "=r"((r)[11]), \
          "=r"((r)[12]), "=r"((r)[13]), "=r"((r)[14]), "=r"((r)[15]), \
          "=r"((r)[16]), "=r"((r)[17]), "=r"((r)[18]), "=r"((r)[19]), \
          "=r"((r)[20]), "=r"((r)[21]), "=r"((r)[22]), "=r"((r)[23]), \
          "=r"((r)[24]), "=r"((r)[25]), "=r"((r)[26]), "=r"((r)[27]), \
          "=r"((r)[28]), "=r"((r)[29]), "=r"((r)[30]), "=r"((r)[31]) \
        : "r"(tmem_addr))

__device__ __forceinline__ void mma_f16_ss(uint32_t d_tmem, uint64_t a_desc,
                                           uint64_t b_desc, uint32_t idesc,
                                           uint32_t enable_d) {
    asm volatile(
        "{\n\t.reg .pred p;\n\t"
        "setp.ne.u32 p, %4, 0;\n\t"
        "tcgen05.mma.cta_group::1.kind::f16 [%0], %1, %2, %3, p;\n\t}"
        :: "r"(d_tmem), "l"(a_desc), "l"(b_desc), "r"(idesc), "r"(enable_d)
        : "memory");
}

#else  // portable-pass stubs (never executed on GB300)

#define TCGEN05_ALLOC(smem_addr, nCols)      do {} while (0)
#define TCGEN05_DEALLOC(tmem_addr, nCols)    do {} while (0)
#define TCGEN05_RELINQUISH()                 do {} while (0)
#define TCGEN05_COMMIT(mbar)                 do {} while (0)
#define TCGEN05_FENCE_AFTER()                do {} while (0)
#define TCGEN05_WAIT_LD()                    do {} while (0)
#define TCGEN05_LD_32X32B_X32(r, tmem_addr) \
    do { _Pragma("unroll") for (int _i = 0; _i < 32; _i++) (r)[_i] = 0u; } while (0)

__device__ __forceinline__ void mma_f16_ss(uint32_t, uint64_t, uint64_t,
                                           uint32_t, uint32_t) {}

#endif  // HAS_TCGEN05

#define FENCE_PROXY_ASYNC_SHARED() \
    asm volatile("fence.proxy.async.shared::cta;" ::: "memory")

#define MBARRIER_INIT(mbar, count) \
    asm volatile("mbarrier.init.shared.b64 [%0], %1;" \
                 :: "r"((uint32_t)(mbar)), "r"((uint32_t)(count)) : "memory")

#define MBARRIER_WAIT_PARITY(mbar_addr, phase_parity) do { \
    uint32_t _mbar = (uint32_t)(mbar_addr); \
    uint32_t _parity = (uint32_t)(phase_parity); \
    uint32_t _done; \
    asm volatile( \
        "{\n\t.reg .pred p;\n\t" \
        "mbarrier.try_wait.parity.acquire.cta.shared::cta.b64 p, [%1], %2;\n\t" \
        "selp.b32 %0, 1, 0, p;\n\t}" \
        : "=r"(_done) : "r"(_mbar), "r"(_parity) : "memory"); \
    if (!_done) { \
        asm volatile( \
            "{\n\t.reg .pred P1;\n\t" \
            "WAIT_LOOP_%=:\n\t" \
            "mbarrier.try_wait.parity.acquire.cta.shared::cta.b64 P1, [%0], %1, 0x989680;\n\t" \
            "@P1 bra.uni WAIT_DONE_%=;\n\t" \
            "bra.uni WAIT_LOOP_%=;\n\t" \
            "WAIT_DONE_%=:\n\t}" \
            :: "r"(_mbar), "r"(_parity) : "memory"); \
    } \
} while (0)

// idesc: F32 accum (1<<4), FP16 a/b, N=256 -> (32<<17), M=128 -> (8<<24)
#define MMA_IDESC 0x8400010u

// ---------------- prep kernels ----------------
__global__ void convert_x_kernel(const float4* __restrict__ x, int n4) {
    int i = blockIdx.x * 256 + threadIdx.x;
    if (i < n4) {
        float4 v = x[i];
        __half2 h0 = __floats2half2_rn(v.x, v.y);
        __half2 h1 = __floats2half2_rn(v.z, v.w);
        uint2 u;
        u.x = *reinterpret_cast<uint32_t*>(&h0);
        u.y = *reinterpret_cast<uint32_t*>(&h1);
        reinterpret_cast<uint2*>(Xh_g)[i] = u;
    }
}

__global__ void quant_w_kernel(const float* __restrict__ W) {
    int o = blockIdx.x * 256 + threadIdx.x;
    if (o < NUM_CHUNKS * C_OUT * K_CHUNK) {
        int col = o & 63;
        int co = (o >> 6) & 255;
        int tc = o >> 14;                       // chunk = tap*2 + half
        int tap = tc >> 1, ch = tc & 1;
        int ci = ch * 64 + col;
        float w = W[(tap * C_IN + ci) * C_OUT + co];
        Wq_g[o] = __float2half(w > 0.f ? 1.f : (w < 0.f ? -1.f : 0.f));
    }
}

// ---------------- main implicit-GEMM conv kernel ----------------
// 2 M-tiles/CTA (shared B), 3-stage cp.async pipeline, 8-warp epilogue.
__global__ void __launch_bounds__(256, 1)
bconv_main_kernel(const float* __restrict__ bias, float* __restrict__ out) {
    extern __shared__ char smem[];
    uint32_t smem_base = smem_u32(smem);
    int tid = threadIdx.x;
    int wid = tid >> 5, lid = tid & 31;

    if (wid == 0) {
        TCGEN05_ALLOC(smem_base + SM_TMEM, 512);
        TCGEN05_RELINQUISH();
    }
    if (tid == 0) {
        MBARRIER_INIT(smem_base + SM_MBAR + 0, 1);
        MBARRIER_INIT(smem_base + SM_MBAR + 8, 1);
        MBARRIER_INIT(smem_base + SM_MBAR + 16, 1);
    }
    __syncthreads();
    uint32_t tmem_base;
    asm volatile("ld.shared.b32 %0, [%1];" : "=r"(tmem_base)
                 : "r"(smem_base + SM_TMEM));

    // per-thread A-fill coordinates: 2 tiles x 4 row-steps
    int hA[8], wA[8];
    size_t rowA[8];
    int seg = tid & 7;                            // 16B segment in 128B row
    int prow = tid >> 3;                          // base row (step 32)
    #pragma unroll
    for (int t = 0; t < 2; t++) {
        int pix_base = blockIdx.x * 256 + t * 128;
        #pragma unroll
        for (int i = 0; i < 4; i++) {
            int gp = pix_base + prow + i * 32;
            int n = gp / PIX_PER_IMG;
            int r = gp % PIX_PER_IMG;
            hA[t * 4 + i] = r / HW_DIM;
            wA[t * 4 + i] = r % HW_DIM;
            rowA[t * 4 + i] = (size_t)n * PIX_PER_IMG * C_IN;
        }
    }

    // async fill of one chunk-stage (all 256 threads, 16 cp.async each)
    auto fill_stage = [&](int c, int buf) {
        int tap = c >> 1, half_k = c & 1;
        int kh = tap / 3 - 1, kw = tap % 3 - 1;
        uint32_t sb = smem_base + SM_STAGE + buf * STAGE_BYTES;
        #pragma unroll
        for (int t = 0; t < 2; t++) {
            #pragma unroll
            for (int i = 0; i < 4; i++) {
                int idx = t * 4 + i;
                int hh = hA[idx] + kh, ww = wA[idx] + kw;
                bool ok = ((unsigned)hh < (unsigned)HW_DIM) &&
                          ((unsigned)ww < (unsigned)HW_DIM);
                const __half* src = Xh_g + rowA[idx] +
                    ((size_t)(ok ? hh : 0) * HW_DIM + (ok ? ww : 0)) * C_IN +
                    half_k * 64 + seg * 8;
                uint32_t off = (uint32_t)(prow + i * 32) * 128 + seg * 16;
                cp_async16(sb + t * A_TILE_B + SW128(off), src, ok);
            }
        }
        const __half* wsrc = Wq_g + (size_t)c * (C_OUT * K_CHUNK);
        #pragma unroll
        for (int i = 0; i < 8; i++) {
            int item = tid + i * 256;             // 0..2047
            uint32_t off = (uint32_t)(item >> 3) * 128 + (item & 7) * 16;
            cp_async16(sb + B_OFF + SW128(off), wsrc + item * 8, true);
        }
    };

    // prologue: stages 0 and 1 in flight
    fill_stage(0, 0); CP_ASYNC_COMMIT();
    fill_stage(1, 1); CP_ASYNC_COMMIT();

    int ph[3] = {0, 0, 0};
    for (int c = 0; c < NUM_CHUNKS; c++) {
        int buf = c % 3;
        if (c < NUM_CHUNKS - 1) { CP_ASYNC_WAIT_1(); } else { CP_ASYNC_WAIT_0(); }
        FENCE_PROXY_ASYNC_SHARED();
        __syncthreads();                          // stage c ready everywhere

        if (wid == 0 && elect_one()) {
            uint32_t sb = smem_base + SM_STAGE + buf * STAGE_BYTES;
            uint64_t a0 = make_desc_sw128(sb);
            uint64_t a1 = make_desc_sw128(sb + A_TILE_B);
            uint64_t bd = make_desc_sw128(sb + B_OFF);
            uint32_t en = (c > 0);
            #pragma unroll
            for (int s = 0; s < 4; s++)
                mma_f16_ss(tmem_base, a0 + s * 2, bd + s * 2,
                           MMA_IDESC, en | (s > 0));
            #pragma unroll
            for (int s = 0; s < 4; s++)
                mma_f16_ss(tmem_base + 256, a1 + s * 2, bd + s * 2,
                           MMA_IDESC, en | (s > 0));
            TCGEN05_COMMIT(smem_base + SM_MBAR + buf * 8);
        }

        if (c + 2 < NUM_CHUNKS) {
            int nb = (c + 2) % 3;                 // == (c-1)%3 for c>=1
            if (c >= 1) {                         // MMA(c-1) must be done
                MBARRIER_WAIT_PARITY(smem_base + SM_MBAR + nb * 8, ph[nb] & 1);
                ph[nb]++;
            }
            fill_stage(c + 2, nb);
            CP_ASYNC_COMMIT();
        }
    }

    // drain last three MMAs
    #pragma unroll
    for (int b = 0; b < 3; b++) {
        MBARRIER_WAIT_PARITY(smem_base + SM_MBAR + b * 8, ph[b] & 1);
    }
    TCGEN05_FENCE_AFTER();

    // ---- epilogue: both warpgroups drain their tile in parallel ----
    float* bsm = reinterpret_cast<float*>(smem + SM_BIAS);
    bsm[tid] = bias[tid];
    __syncthreads();

    int wg = wid >> 2;                            // tile index
    int sp = wid & 3;                             // subpartition
    float* tb = reinterpret_cast<float*>(smem + SM_TBUF) + wg * TBUF_FLT;
    float* tb_all = reinterpret_cast<float*>(smem + SM_TBUF);

    #pragma unroll 1
    for (int cb = 0; cb < 8; cb++) {
        uint32_t regs[32];
        TCGEN05_LD_32X32B_X32(regs, tmem_base + wg * 256 + cb * 32);
        TCGEN05_WAIT_LD();
        int row = sp * 32 + lid;
        #pragma unroll
        for (int j = 0; j < 32; j++)
            tb[row * 33 + j] = __uint_as_float(regs[j]) + bsm[cb * 32 + j];
        __syncthreads();
        #pragma unroll
        for (int i = 0; i < 32; i++) {
            int item = tid + i * 256;             // 0..8191 = 2 tiles x 128 x 32
            int t2 = item >> 12, rem = item & 4095;
            int p = rem >> 5, cc = rem & 31;
            out[(size_t)(blockIdx.x * 256 + t2 * 128 + p) * C_OUT + cb * 32 + cc] =
                tb_all[t2 * TBUF_FLT + p * 33 + cc];
        }
        __syncthreads();
    }

    if (wid == 0) {
        TCGEN05_DEALLOC(tmem_base, 512);
    }
}

// ---------------- launch ----------------
extern "C" void kernel_launch(void* const* d_in, const int* in_sizes, int n_in,
                              void* d_out, int out_size) {
    const float* x = (const float*)d_in[0];
    const float* W = (const float*)d_in[1];
    const float* b = (const float*)d_in[2];
    float* out = (float*)d_out;

    cudaFuncSetAttribute(bconv_main_kernel,
                         cudaFuncAttributeMaxDynamicSharedMemorySize, SM_TOTAL);

    int n4 = (TOT_PIX * C_IN) / 4;
    convert_x_kernel<<<n4 / 256, 256>>>(reinterpret_cast<const float4*>(x), n4);
    quant_w_kernel<<<(NUM_CHUNKS * C_OUT * K_CHUNK) / 256, 256>>>(W);
    bconv_main_kernel<<<NUM_PAIRS, 256, SM_TOTAL>>>(b, out);
}